// round 13
// baseline (speedup 1.0000x reference)
#include <cuda_runtime.h>
#include <stdint.h>

#define BB   256          // batch (images / segments)
#define DD   512          // embedding dim
#define HWQ  256          // H*W spatial positions
#define NT   256          // threads per block
#define DH   256          // d-half size (DD/2)
#define DH4  64           // float4s per half-vector

__device__ __forceinline__ uint32_t smem_u32(const void* p) {
    uint32_t a;
    asm("{ .reg .u64 t; cvta.to.shared.u64 t, %1; cvt.u32.u64 %0, t; }"
        : "=r"(a) : "l"(p));
    return a;
}
__device__ __forceinline__ void bulk_store(void* gdst, uint32_t ssrc, uint32_t bytes) {
    asm volatile("cp.async.bulk.global.shared::cta.bulk_group [%0], [%1], %2;"
                 :: "l"(gdst), "r"(ssrc), "r"(bytes) : "memory");
}
__device__ __forceinline__ void bulk_commit() {
    asm volatile("cp.async.bulk.commit_group;" ::: "memory");
}
__device__ __forceinline__ void bulk_wait0() {
    asm volatile("cp.async.bulk.wait_group 0;" ::: "memory");
}

// ---------------------------------------------------------------------------
// 512 blocks x 256 threads. Block k = (item<<1)|h handles BOTH:
//   snd half-item (b=item, h): scan splits in-smem (dtype-robust), reduce
//       cols [256h,+256) of segment b (128 KiB read), issue 256 x 1 KiB TMA
//       bulk stores of M_snd[b,:,256h:+256)  -- COMMIT, DO NOT WAIT.
//   img half-item (j=item, h): reduce d-rows [256h,+256) of Z_img[j]
//       (256 KiB read, overlapping the snd writes still in flight), issue
//       256 x 1 KiB stores of M_img[:,j,256h:+256), then wait for ALL.
// Intra-block overlap: snd write phase flies under img read phase.
// Output layout: [ M_img (B,B,D) | M_snd (B,B,D) ].
// ---------------------------------------------------------------------------
__global__ __launch_bounds__(NT, 8)
void fused_meanpool_bcast(const float* __restrict__ Zimg,
                          const float* __restrict__ Zsnd,
                          const int*   __restrict__ splits,
                          float*       __restrict__ out,
                          long long T) {
    __shared__ long long s_scan[BB];                   // 2 KiB
    __shared__ float4    s_part[4][DH4];               // 4 KiB
    __shared__ __align__(16) float s_sndvec[DH];       // 1 KiB (stable during TMA)
    __shared__ __align__(16) float s_imgvec[DH];       // 1 KiB

    const int t    = threadIdx.x;
    const int wid  = t >> 5;
    const int lane = t & 31;
    const int item = blockIdx.x >> 1;                  // 0..255
    const int h    = blockIdx.x & 1;                   // d-half
    const size_t NIMG = (size_t)BB * BB * DD;          // floats in M_img

    // ========== PHASE 1: SND half-item (b = item, h) ==========
    {
        const int b = item;

        // --- in-block inclusive scan of splits (dtype-robust) ---
        s_scan[t] = (long long)splits[t];
        __syncthreads();
#pragma unroll
        for (int off = 1; off < BB; off <<= 1) {
            long long v = (t >= off) ? s_scan[t - off] : 0LL;
            __syncthreads();
            s_scan[t] += v;
            __syncthreads();
        }
        if (s_scan[BB - 1] != T) {
            const long long* p64 = (const long long*)splits;
            __syncthreads();
            s_scan[t] = p64[t];
            __syncthreads();
#pragma unroll
            for (int off = 1; off < BB; off <<= 1) {
                long long v = (t >= off) ? s_scan[t - off] : 0LL;
                __syncthreads();
                s_scan[t] += v;
                __syncthreads();
            }
        }
        __syncthreads();
        const long long start = (b == 0) ? 0LL : s_scan[b - 1];
        const long long len   = s_scan[b] - start;

        // --- reduce cols [64h..64h+64) float4 over segment rows ---
        const int col   = t & (DH4 - 1);               // 0..63
        const int slice = t >> 6;                      // 0..3
        long long r0 = start + (len * slice)       / 4;
        long long r1 = start + (len * (slice + 1)) / 4;

        const float4* p = reinterpret_cast<const float4*>(Zsnd);
        float4 acc0 = make_float4(0.f, 0.f, 0.f, 0.f);
        float4 acc1 = make_float4(0.f, 0.f, 0.f, 0.f);
        long long r = r0;
        for (; r + 1 < r1; r += 2) {
            float4 v0 = __ldcs(&p[r       * (DD / 4) + h * DH4 + col]);
            float4 v1 = __ldcs(&p[(r + 1) * (DD / 4) + h * DH4 + col]);
            acc0.x += v0.x; acc0.y += v0.y; acc0.z += v0.z; acc0.w += v0.w;
            acc1.x += v1.x; acc1.y += v1.y; acc1.z += v1.z; acc1.w += v1.w;
        }
        if (r < r1) {
            float4 v0 = __ldcs(&p[r * (DD / 4) + h * DH4 + col]);
            acc0.x += v0.x; acc0.y += v0.y; acc0.z += v0.z; acc0.w += v0.w;
        }
        acc0.x += acc1.x; acc0.y += acc1.y; acc0.z += acc1.z; acc0.w += acc1.w;
        s_part[slice][col] = acc0;
        __syncthreads();

        if (slice == 0) {
            float4 a0 = s_part[0][col], a1 = s_part[1][col],
                   a2 = s_part[2][col], a3 = s_part[3][col];
            float inv = (len > 0) ? (1.0f / (float)len) : 0.0f;
            float4 o;
            o.x = (a0.x + a1.x + a2.x + a3.x) * inv;
            o.y = (a0.y + a1.y + a2.y + a3.y) * inv;
            o.z = (a0.z + a1.z + a2.z + a3.z) * inv;
            o.w = (a0.w + a1.w + a2.w + a3.w) * inv;
            reinterpret_cast<float4*>(s_sndvec)[col] = o;
        }
        __syncthreads();
        asm volatile("fence.proxy.async.shared::cta;" ::: "memory");

        // issue snd writes: 256 rows x 1 KiB at 2 KiB stride -- NO WAIT
        if (lane == 0) {
            uint32_t src = smem_u32(s_sndvec);
            char* dst0 = (char*)out + (NIMG
                       + (size_t)b * BB * DD + (size_t)h * DH) * 4;
            const size_t STR = (size_t)DD * 4;         // 2 KiB
#pragma unroll 4
            for (int k = 0; k < 32; ++k) {
                int i = wid * 32 + k;
                bulk_store(dst0 + (size_t)i * STR, src, DH * 4);
            }
            bulk_commit();
        }
    }

    // ========== PHASE 2: IMG half-item (j = item, h) — overlaps snd writes ==========
    {
        const int j = item;

        const float4* p = reinterpret_cast<const float4*>(
            Zimg + ((size_t)j * DD + (size_t)h * DH) * HWQ);

        // 8 warps x 32 rows; 2 rows per iter (4 independent loads) for MLP
        for (int k = 0; k < 16; ++k) {
            int lr0 = wid * 32 + 2 * k;
            int lr1 = lr0 + 1;
            float4 a0 = __ldcs(&p[(size_t)lr0 * 64 + lane]);
            float4 b0 = __ldcs(&p[(size_t)lr0 * 64 + 32 + lane]);
            float4 a1 = __ldcs(&p[(size_t)lr1 * 64 + lane]);
            float4 b1 = __ldcs(&p[(size_t)lr1 * 64 + 32 + lane]);
            float s0 = (a0.x + a0.y) + (a0.z + a0.w) + (b0.x + b0.y) + (b0.z + b0.w);
            float s1 = (a1.x + a1.y) + (a1.z + a1.w) + (b1.x + b1.y) + (b1.z + b1.w);
#pragma unroll
            for (int o = 16; o > 0; o >>= 1) {
                s0 += __shfl_down_sync(0xffffffffu, s0, o);
                s1 += __shfl_down_sync(0xffffffffu, s1, o);
            }
            if (lane == 0) {
                s_imgvec[lr0] = s0 * (1.0f / (float)HWQ);
                s_imgvec[lr1] = s1 * (1.0f / (float)HWQ);
            }
        }
        __syncthreads();
        asm volatile("fence.proxy.async.shared::cta;" ::: "memory");

        // issue img writes: 256 rows x 1 KiB at 512 KiB stride, then wait ALL
        if (lane == 0) {
            uint32_t src = smem_u32(s_imgvec);
            char* dst0 = (char*)out + ((size_t)j * DD + (size_t)h * DH) * 4;
            const size_t STR = (size_t)BB * DD * 4;    // 512 KiB
#pragma unroll 4
            for (int k = 0; k < 32; ++k) {
                int i = wid * 32 + k;
                bulk_store(dst0 + (size_t)i * STR, src, DH * 4);
            }
            bulk_commit();
            bulk_wait0();          // drains snd + img groups
        }
    }
}

// ---------------------------------------------------------------------------
extern "C" void kernel_launch(void* const* d_in, const int* in_sizes, int n_in,
                              void* d_out, int out_size) {
    // Identify inputs by element count:
    //   Z_img: 33,554,432   Z_snd: 16,777,216   splits: 256
    const float* Zimg   = nullptr;
    const float* Zsnd   = nullptr;
    const int*   splits = nullptr;
    long long    Tsnd   = 0;

    for (int i = 0; i < n_in; ++i) {
        if (in_sizes[i] == BB) {
            splits = (const int*)d_in[i];
        } else if (in_sizes[i] == BB * DD * HWQ) {
            Zimg = (const float*)d_in[i];
        } else {
            Zsnd = (const float*)d_in[i];
            Tsnd = (long long)(in_sizes[i] / DD);
        }
    }
    (void)out_size;

    fused_meanpool_bcast<<<512, NT>>>(Zimg, Zsnd, splits,
                                      (float*)d_out, Tsnd);
}

// round 14
// speedup vs baseline: 1.1050x; 1.1050x over previous
#include <cuda_runtime.h>
#include <stdint.h>

#define BB   256          // batch (images / segments)
#define DD   512          // embedding dim
#define HWQ  256          // H*W spatial positions
#define NT   256          // threads per block
#define DH   256          // d-half size (DD/2)
#define DH4  64           // float4s per half-vector

__device__ __forceinline__ uint32_t smem_u32(const void* p) {
    uint32_t a;
    asm("{ .reg .u64 t; cvta.to.shared.u64 t, %1; cvt.u32.u64 %0, t; }"
        : "=r"(a) : "l"(p));
    return a;
}
__device__ __forceinline__ uint64_t mkpolicy_evict_last() {
    uint64_t p; asm("createpolicy.fractional.L2::evict_last.b64 %0, 1.0;" : "=l"(p)); return p;
}
__device__ __forceinline__ uint64_t mkpolicy_evict_first() {
    uint64_t p; asm("createpolicy.fractional.L2::evict_first.b64 %0, 1.0;" : "=l"(p)); return p;
}
__device__ __forceinline__ float4 ldg_pol(const float4* p, uint64_t pol) {
    float4 v;
    asm volatile("ld.global.L2::cache_hint.v4.f32 {%0,%1,%2,%3}, [%4], %5;"
                 : "=f"(v.x), "=f"(v.y), "=f"(v.z), "=f"(v.w)
                 : "l"(p), "l"(pol));
    return v;
}
__device__ __forceinline__ void bulk_store(void* gdst, uint32_t ssrc,
                                           uint32_t bytes, uint64_t pol) {
    asm volatile("cp.async.bulk.global.shared::cta.bulk_group.L2::cache_hint "
                 "[%0], [%1], %2, %3;"
                 :: "l"(gdst), "r"(ssrc), "r"(bytes), "l"(pol) : "memory");
}
__device__ __forceinline__ void bulk_commit() {
    asm volatile("cp.async.bulk.commit_group;" ::: "memory");
}
__device__ __forceinline__ void bulk_wait0() {
    asm volatile("cp.async.bulk.wait_group 0;" ::: "memory");
}

// ---------------------------------------------------------------------------
// 1024 uniform blocks x 256 threads, single wave at 8 blocks/SM.
//   bid in [0,512)    : img item (j = bid>>1, h = bid&1)
//       reduce d-rows [256h,256h+256) of Z_img[j]  (256 KiB contiguous read)
//       write M_img[i, j, 256h:256h+256) for all i (256 x 1 KiB, stride 512 KiB)
//   bid in [512,1024) : snd item (b = (bid-512)>>1, h)
//       scan splits in-smem (dtype-robust), reduce cols [256h,256h+256) of
//       segment b (128 KiB read), write M_snd[b, :, 256h:...) (256 x 1 KiB,
//       stride 2 KiB)
// All stores are TMA bulk (evict_first); snd reads evict_last, img evict_first.
// Output layout: [ M_img (B,B,D) | M_snd (B,B,D) ].
// Validated optimum: 6.35 TB/s effective (~80% HBM spec) on the 448 MiB
// compulsory stream; STG stores, 16 KiB stores, tensor-TMA, parity interleave
// and write-under-read pairing all measured slower (R9-R13).
// ---------------------------------------------------------------------------
__global__ __launch_bounds__(NT, 8)
void fused_meanpool_bcast(const float* __restrict__ Zimg,
                          const float* __restrict__ Zsnd,
                          const int*   __restrict__ splits,
                          float*       __restrict__ out,
                          long long T) {
    __shared__ long long s_scan[BB];                   // 2 KiB (snd only)
    __shared__ float4    s_part[4][DH4];               // 4 KiB (snd only)
    __shared__ __align__(16) float s_half[DH];         // 1 KiB half-vector

    const int t    = threadIdx.x;
    const int wid  = t >> 5;
    const int lane = t & 31;
    const uint64_t pol_wr = mkpolicy_evict_first();
    const size_t NIMG_BYTES = (size_t)BB * BB * DD * 4;   // 128 MiB

    if (blockIdx.x < 512) {
        // =================== IMG ITEM ===================
        const int j = blockIdx.x >> 1;
        const int h = blockIdx.x & 1;
        const uint64_t pol_rd = mkpolicy_evict_first();

        // rows [256h, 256h+256): contiguous 256 KiB slab
        const float4* p = reinterpret_cast<const float4*>(
            Zimg + ((size_t)j * DD + (size_t)h * DH) * HWQ);

        // 8 warps x 32 rows each; per row: 64 float4, 2 per lane
        for (int k = 0; k < 32; ++k) {
            int lr = wid * 32 + k;                     // local d-row 0..255
            float4 a = ldg_pol(&p[(size_t)lr * 64 + lane],      pol_rd);
            float4 b = ldg_pol(&p[(size_t)lr * 64 + 32 + lane], pol_rd);
            float s = (a.x + a.y) + (a.z + a.w) + (b.x + b.y) + (b.z + b.w);
#pragma unroll
            for (int o = 16; o > 0; o >>= 1)
                s += __shfl_down_sync(0xffffffffu, s, o);
            if (lane == 0)
                s_half[lr] = s * (1.0f / (float)HWQ);
        }
        __syncthreads();
        asm volatile("fence.proxy.async.shared::cta;" ::: "memory");

        // write 256 rows x 1 KiB at 512 KiB stride
        if (lane == 0) {
            uint32_t src = smem_u32(s_half);
            char* dst0 = (char*)out + ((size_t)j * DD + (size_t)h * DH) * 4;
            const size_t STR = (size_t)BB * DD * 4;    // 512 KiB
#pragma unroll 4
            for (int k = 0; k < 32; ++k) {
                int i = wid * 32 + k;
                bulk_store(dst0 + (size_t)i * STR, src, DH * 4, pol_wr);
            }
            bulk_commit();
            bulk_wait0();
        }

    } else {
        // =================== SND ITEM ===================
        const int id = blockIdx.x - 512;
        const int b  = id >> 1;
        const int h  = id & 1;
        const uint64_t pol_rd = mkpolicy_evict_last();

        // --- in-block inclusive scan of splits (dtype-robust) ---
        s_scan[t] = (long long)splits[t];
        __syncthreads();
#pragma unroll
        for (int off = 1; off < BB; off <<= 1) {
            long long v = (t >= off) ? s_scan[t - off] : 0LL;
            __syncthreads();
            s_scan[t] += v;
            __syncthreads();
        }
        if (s_scan[BB - 1] != T) {
            const long long* p64 = (const long long*)splits;
            __syncthreads();
            s_scan[t] = p64[t];
            __syncthreads();
#pragma unroll
            for (int off = 1; off < BB; off <<= 1) {
                long long v = (t >= off) ? s_scan[t - off] : 0LL;
                __syncthreads();
                s_scan[t] += v;
                __syncthreads();
            }
        }
        __syncthreads();
        const long long start = (b == 0) ? 0LL : s_scan[b - 1];
        const long long len   = s_scan[b] - start;

        // --- reduce cols [64h..64h+64) float4 over segment rows ---
        const int col   = t & (DH4 - 1);               // 0..63
        const int slice = t >> 6;                      // 0..3
        long long r0 = start + (len * slice)       / 4;
        long long r1 = start + (len * (slice + 1)) / 4;

        const float4* p = reinterpret_cast<const float4*>(Zsnd);
        float4 acc = make_float4(0.f, 0.f, 0.f, 0.f);
        for (long long r = r0; r < r1; ++r) {
            float4 v = ldg_pol(&p[r * (DD / 4) + h * DH4 + col], pol_rd);
            acc.x += v.x; acc.y += v.y; acc.z += v.z; acc.w += v.w;
        }
        s_part[slice][col] = acc;
        __syncthreads();

        if (slice == 0) {
            float4 a0 = s_part[0][col], a1 = s_part[1][col],
                   a2 = s_part[2][col], a3 = s_part[3][col];
            float inv = (len > 0) ? (1.0f / (float)len) : 0.0f;
            float4 o;
            o.x = (a0.x + a1.x + a2.x + a3.x) * inv;
            o.y = (a0.y + a1.y + a2.y + a3.y) * inv;
            o.z = (a0.z + a1.z + a2.z + a3.z) * inv;
            o.w = (a0.w + a1.w + a2.w + a3.w) * inv;
            reinterpret_cast<float4*>(s_half)[col] = o;
        }
        __syncthreads();
        asm volatile("fence.proxy.async.shared::cta;" ::: "memory");

        // write 256 rows x 1 KiB at 2 KiB stride
        if (lane == 0) {
            uint32_t src = smem_u32(s_half);
            char* dst0 = (char*)out + NIMG_BYTES
                       + ((size_t)b * BB * DD + (size_t)h * DH) * 4;
            const size_t STR = (size_t)DD * 4;         // 2 KiB
#pragma unroll 4
            for (int k = 0; k < 32; ++k) {
                int i = wid * 32 + k;
                bulk_store(dst0 + (size_t)i * STR, src, DH * 4, pol_wr);
            }
            bulk_commit();
            bulk_wait0();
        }
    }
}

// ---------------------------------------------------------------------------
extern "C" void kernel_launch(void* const* d_in, const int* in_sizes, int n_in,
                              void* d_out, int out_size) {
    // Identify inputs by element count:
    //   Z_img: 33,554,432   Z_snd: 16,777,216   splits: 256
    const float* Zimg   = nullptr;
    const float* Zsnd   = nullptr;
    const int*   splits = nullptr;
    long long    Tsnd   = 0;

    for (int i = 0; i < n_in; ++i) {
        if (in_sizes[i] == BB) {
            splits = (const int*)d_in[i];
        } else if (in_sizes[i] == BB * DD * HWQ) {
            Zimg = (const float*)d_in[i];
        } else {
            Zsnd = (const float*)d_in[i];
            Tsnd = (long long)(in_sizes[i] / DD);
        }
    }
    (void)out_size;

    fused_meanpool_bcast<<<1024, NT>>>(Zimg, Zsnd, splits,
                                       (float*)d_out, Tsnd);
}